// round 6
// baseline (speedup 1.0000x reference)
#include <cuda_runtime.h>
#include <cuda_fp16.h>
#include <cstdint>

#define NUM_HEADS 12
#define NUM_BN 4
#define HIDDEN 768
#define HEAD_DIM 64
#define BATCH 8
#define SEQ 8192
#define NROW 48
#define SCALE 0.125f
#define KCH_CTX 8
#define TOK_PER_KC (SEQ / KCH_CTX)   // 1024

// ---------------- scratch -------------------------------------------------
__device__ float  g_q[BATCH * NUM_BN * HIDDEN];
__device__ __half g_qk[BATCH * NROW * HIDDEN];
__device__ float  g_logits[(size_t)BATCH * NROW * SEQ];
__device__ __half g_probs[(size_t)BATCH * NROW * SEQ];
__device__ float  g_ctxp[(size_t)KCH_CTX * BATCH * NROW * HIDDEN];
__device__ float  g_o[BATCH * NUM_BN * HIDDEN];

// ---------------- helpers -------------------------------------------------
__device__ __forceinline__ void mma_f16(float* d, const uint32_t* a, const uint32_t* b) {
    asm volatile(
        "mma.sync.aligned.m16n8k16.row.col.f32.f16.f16.f32 "
        "{%0,%1,%2,%3}, {%4,%5,%6,%7}, {%8,%9}, {%0,%1,%2,%3};"
        : "+f"(d[0]), "+f"(d[1]), "+f"(d[2]), "+f"(d[3])
        : "r"(a[0]), "r"(a[1]), "r"(a[2]), "r"(a[3]), "r"(b[0]), "r"(b[1]));
}
__device__ __forceinline__ uint32_t packh2(float lo, float hi) {
    uint32_t r;
    asm("cvt.rn.f16x2.f32 %0, %1, %2;" : "=r"(r) : "f"(hi), "f"(lo));
    return r;
}
__device__ __forceinline__ void cp16(void* dst_smem, const void* src_gmem) {
    uint32_t d = (uint32_t)__cvta_generic_to_shared(dst_smem);
    asm volatile("cp.async.cg.shared.global [%0], [%1], 16;" :: "r"(d), "l"(src_gmem));
}
__device__ __forceinline__ void cp_commit() { asm volatile("cp.async.commit_group;"); }
__device__ __forceinline__ void cp_wait1() { asm volatile("cp.async.wait_group 1;"); }
__device__ __forceinline__ void cp_wait0() { asm volatile("cp.async.wait_group 0;"); }

// ---------------- K1: q = x[:, :4] @ w_q^T (split in two launches) ---------
__global__ void __launch_bounds__(256) k_qproj(const float* __restrict__ x,
                                               const float* __restrict__ wq,
                                               int obase) {
    __shared__ float sX[4][HIDDEN];
    __shared__ float sW[128][65];
    int b = blockIdx.y, o0 = (obase + blockIdx.x) * 128;
    int tid = threadIdx.x;
    for (int i = tid; i < 4 * HIDDEN; i += 256) {
        int r = i / HIDDEN, c = i % HIDDEN;
        sX[r][c] = x[((size_t)b * SEQ + r) * HIDDEN + c];
    }
    int ol = tid & 127, xp = tid >> 7;
    float acc0 = 0.f, acc1 = 0.f;
    for (int kc = 0; kc < 12; kc++) {
        int k0 = kc * 64;
        __syncthreads();
        for (int i = tid; i < 128 * 64; i += 256) {
            int r = i >> 6, c = i & 63;
            sW[r][c] = wq[(size_t)(o0 + r) * HIDDEN + k0 + c];
        }
        __syncthreads();
#pragma unroll 8
        for (int kk = 0; kk < 64; kk++) {
            float w = sW[ol][kk];
            acc0 += sX[xp * 2][k0 + kk] * w;
            acc1 += sX[xp * 2 + 1][k0 + kk] * w;
        }
    }
    g_q[(size_t)(b * 4 + xp * 2) * HIDDEN + o0 + ol] = acc0;
    g_q[(size_t)(b * 4 + xp * 2 + 1) * HIDDEN + o0 + ol] = acc1;
}

// ---------------- K2: qk = SCALE * q_h @ Wk_h -> fp16 ----------------------
__global__ void __launch_bounds__(256) k_qk(const float* __restrict__ wkv) {
    int h = blockIdx.x, b = blockIdx.y;
    __shared__ float sQ[4][64];
    __shared__ float sW[32][257];
    int tid = threadIdx.x;
    {
        int xx = tid >> 6, d = tid & 63;
        sQ[xx][d] = g_q[(size_t)(b * 4 + xx) * HIDDEN + h * 64 + d];
    }
    for (int n0 = 0; n0 < HIDDEN; n0 += 256) {
        float a0 = 0.f, a1 = 0.f, a2 = 0.f, a3 = 0.f;
        for (int kc = 0; kc < 2; kc++) {
            __syncthreads();
            for (int i = tid; i < 32 * 256; i += 256) {
                int r = i >> 8, c = i & 255;
                sW[r][c] = wkv[(size_t)(h * 64 + kc * 32 + r) * HIDDEN + n0 + c];
            }
            __syncthreads();
#pragma unroll
            for (int d = 0; d < 32; d++) {
                float w = sW[d][tid];
                int kd = kc * 32 + d;
                a0 += sQ[0][kd] * w;
                a1 += sQ[1][kd] * w;
                a2 += sQ[2][kd] * w;
                a3 += sQ[3][kd] * w;
            }
        }
        size_t rb = (size_t)(b * NROW + h * 4) * HIDDEN + n0 + tid;
        g_qk[rb] = __float2half(a0 * SCALE);
        g_qk[rb + HIDDEN] = __float2half(a1 * SCALE);
        g_qk[rb + 2 * HIDDEN] = __float2half(a2 * SCALE);
        g_qk[rb + 3 * HIDDEN] = __float2half(a3 * SCALE);
    }
}

// ---------------- K3: logits = qk @ x^T, fp16 mma, pipelined (R3 geom) -----
// grid (32 token-tiles, 8 b), 256 thr. Tile M=48, N=256, K=768 (chunks of 32).
#define LQ_ST 20
#define LX_ST 36
#define LQ_SZ (48 * LQ_ST)
#define LX_SZ (256 * LX_ST)
__global__ void __launch_bounds__(256) k_logits(const float* __restrict__ x) {
    extern __shared__ uint32_t sm32[];
    float* smf = (float*)sm32;
    int b = blockIdx.y;
    int tok0 = blockIdx.x * 256;
    int tid = threadIdx.x;
    int warp = tid >> 5, lane = tid & 31;
    int g = lane >> 2, t = lane & 3;
    const float* xb = x + (size_t)b * SEQ * HIDDEN;
    const __half* qb = g_qk + (size_t)b * NROW * HIDDEN;

    float acc[3][4][4];
#pragma unroll
    for (int m = 0; m < 3; m++)
#pragma unroll
        for (int n = 0; n < 4; n++)
#pragma unroll
            for (int i = 0; i < 4; i++) acc[m][n][i] = 0.f;

    auto stage = [&](int kc, int s) {
        int k0 = kc * 32;
        if (tid < 192) {
            int r = tid >> 2, c4 = tid & 3;
            cp16(sm32 + s * LQ_SZ + r * LQ_ST + c4 * 4,
                 qb + (size_t)r * HIDDEN + k0 + c4 * 8);
        }
        uint32_t* xs = sm32 + 2 * LQ_SZ + s * LX_SZ;
#pragma unroll
        for (int i = 0; i < 8; i++) {
            int idx = tid + i * 256;
            int r = idx >> 3, c4 = idx & 7;
            cp16(xs + r * LX_ST + c4 * 4, xb + (size_t)(tok0 + r) * HIDDEN + k0 + c4 * 4);
        }
        cp_commit();
    };

    stage(0, 0);
    for (int kc = 0; kc < 24; kc++) {
        int s = kc & 1;
        if (kc + 1 < 24) { stage(kc + 1, s ^ 1); cp_wait1(); }
        else             { cp_wait0(); }
        __syncthreads();
        const uint32_t* q = sm32 + s * LQ_SZ;
        const float* xs = smf + 2 * LQ_SZ + s * LX_SZ;
#pragma unroll
        for (int ks = 0; ks < 2; ks++) {
            int kk = ks * 16, kk2 = ks * 8;
            uint32_t a[3][4], bb[4][2];
#pragma unroll
            for (int m = 0; m < 3; m++) {
                int r0 = m * 16 + g;
                a[m][0] = q[r0 * LQ_ST + kk2 + t];
                a[m][1] = q[(r0 + 8) * LQ_ST + kk2 + t];
                a[m][2] = q[r0 * LQ_ST + kk2 + t + 4];
                a[m][3] = q[(r0 + 8) * LQ_ST + kk2 + t + 4];
            }
#pragma unroll
            for (int n = 0; n < 4; n++) {
                int row = warp * 32 + n * 8 + g;
                float2 p0 = *(const float2*)(xs + row * LX_ST + kk + 2 * t);
                float2 p1 = *(const float2*)(xs + row * LX_ST + kk + 2 * t + 8);
                bb[n][0] = packh2(p0.x, p0.y);
                bb[n][1] = packh2(p1.x, p1.y);
            }
#pragma unroll
            for (int m = 0; m < 3; m++)
#pragma unroll
                for (int n = 0; n < 4; n++) mma_f16(acc[m][n], a[m], bb[n]);
        }
        __syncthreads();
    }
#pragma unroll
    for (int m = 0; m < 3; m++)
#pragma unroll
        for (int n = 0; n < 4; n++) {
            int r = m * 16 + g;
            int col = tok0 + warp * 32 + n * 8 + t * 2;
            *(float2*)(g_logits + ((size_t)b * NROW + r) * SEQ + col) =
                make_float2(acc[m][n][0], acc[m][n][1]);
            *(float2*)(g_logits + ((size_t)b * NROW + r + 8) * SEQ + col) =
                make_float2(acc[m][n][2], acc[m][n][3]);
        }
}

// ---------------- K4: softmax: fp32 logits -> fp16 probs -------------------
__global__ void __launch_bounds__(512) k_rowstats() {
    int row = blockIdx.x;
    const float* lp = g_logits + (size_t)row * SEQ;
    __half2* pp = (__half2*)(g_probs + (size_t)row * SEQ);
    int tid = threadIdx.x;
    float4 v[4];
#pragma unroll
    for (int i = 0; i < 4; i++) v[i] = ((const float4*)lp)[i * 512 + tid];

    float m = -3.4e38f;
#pragma unroll
    for (int i = 0; i < 4; i++)
        m = fmaxf(m, fmaxf(fmaxf(v[i].x, v[i].y), fmaxf(v[i].z, v[i].w)));
    __shared__ float red[16];
#pragma unroll
    for (int o = 16; o > 0; o >>= 1) m = fmaxf(m, __shfl_xor_sync(0xffffffffu, m, o));
    if ((tid & 31) == 0) red[tid >> 5] = m;
    __syncthreads();
    if (tid < 32) {
        float v2 = (tid < 16) ? red[tid] : -3.4e38f;
#pragma unroll
        for (int o = 8; o > 0; o >>= 1) v2 = fmaxf(v2, __shfl_xor_sync(0xffffffffu, v2, o));
        if (tid == 0) red[0] = v2;
    }
    __syncthreads();
    m = red[0];

    float s = 0.f;
#pragma unroll
    for (int i = 0; i < 4; i++) {
        v[i].x = __expf(v[i].x - m);
        v[i].y = __expf(v[i].y - m);
        v[i].z = __expf(v[i].z - m);
        v[i].w = __expf(v[i].w - m);
        s += (v[i].x + v[i].y) + (v[i].z + v[i].w);
    }
    __shared__ float red2[16];
#pragma unroll
    for (int o = 16; o > 0; o >>= 1) s += __shfl_xor_sync(0xffffffffu, s, o);
    if ((tid & 31) == 0) red2[tid >> 5] = s;
    __syncthreads();
    if (tid < 32) {
        float v2 = (tid < 16) ? red2[tid] : 0.f;
#pragma unroll
        for (int o = 8; o > 0; o >>= 1) v2 += __shfl_xor_sync(0xffffffffu, v2, o);
        if (tid == 0) red2[0] = v2;
    }
    __syncthreads();
    float inv = 1.0f / red2[0];

#pragma unroll
    for (int i = 0; i < 4; i++) {
        int idx = i * 512 + tid;
        pp[idx * 2 + 0] = __floats2half2_rn(v[i].x * inv, v[i].y * inv);
        pp[idx * 2 + 1] = __floats2half2_rn(v[i].z * inv, v[i].w * inv);
    }
}

// ---------------- K5: ctx partials = probs @ x, fp16 mma (R3 geom) ---------
// grid (3 ntile, 8 kchunk, 8 b), 256 thr. Tile M=48, N=256, K=1024 tokens.
#define CA_ST 20
#define CX_ST 260
#define CA_SZ (48 * CA_ST)
#define CX_SZ (32 * CX_ST)
__global__ void __launch_bounds__(256) k_ctx(const float* __restrict__ x) {
    extern __shared__ uint32_t sm32[];
    float* smf = (float*)sm32;
    int nt = blockIdx.x;
    int kc = blockIdx.y;
    int b = blockIdx.z;
    int tid = threadIdx.x;
    int warp = tid >> 5, lane = tid & 31;
    int g = lane >> 2, t = lane & 3;
    int tokbase = kc * TOK_PER_KC;
    const __half* pb = g_probs + (size_t)b * NROW * SEQ;
    const float* xb = x + ((size_t)b * SEQ) * HIDDEN + nt * 256;

    float acc[3][4][4];
#pragma unroll
    for (int m = 0; m < 3; m++)
#pragma unroll
        for (int n = 0; n < 4; n++)
#pragma unroll
            for (int i = 0; i < 4; i++) acc[m][n][i] = 0.f;

    auto stage = [&](int ch, int s) {
        int tok0 = tokbase + ch * 32;
        if (tid < 192) {
            int r = tid >> 2, c4 = tid & 3;
            cp16(sm32 + s * CA_SZ + r * CA_ST + c4 * 4,
                 pb + (size_t)r * SEQ + tok0 + c4 * 8);
        }
        uint32_t* xs = sm32 + 2 * CA_SZ + s * CX_SZ;
#pragma unroll
        for (int i = 0; i < 8; i++) {
            int idx = tid + i * 256;
            int r = idx >> 6, c4 = idx & 63;
            cp16(xs + r * CX_ST + c4 * 4, xb + (size_t)(tok0 + r) * HIDDEN + c4 * 4);
        }
        cp_commit();
    };

    const int NCH = TOK_PER_KC / 32;   // 32
    stage(0, 0);
    for (int ch = 0; ch < NCH; ch++) {
        int s = ch & 1;
        if (ch + 1 < NCH) { stage(ch + 1, s ^ 1); cp_wait1(); }
        else              { cp_wait0(); }
        __syncthreads();
        const uint32_t* a = sm32 + s * CA_SZ;
        const float* xs = smf + 2 * CA_SZ + s * CX_SZ;
#pragma unroll
        for (int ks = 0; ks < 2; ks++) {
            int kk = ks * 16, kk2 = ks * 8;
            uint32_t af[3][4], bb[4][2];
#pragma unroll
            for (int m = 0; m < 3; m++) {
                int r0 = m * 16 + g;
                af[m][0] = a[r0 * CA_ST + kk2 + t];
                af[m][1] = a[(r0 + 8) * CA_ST + kk2 + t];
                af[m][2] = a[r0 * CA_ST + kk2 + t + 4];
                af[m][3] = a[(r0 + 8) * CA_ST + kk2 + t + 4];
            }
#pragma unroll
            for (int n = 0; n < 4; n++) {
                int col = warp * 32 + n * 8 + g;
                float f0 = xs[(kk + 2 * t) * CX_ST + col];
                float f1 = xs[(kk + 2 * t + 1) * CX_ST + col];
                float f2 = xs[(kk + 2 * t + 8) * CX_ST + col];
                float f3 = xs[(kk + 2 * t + 9) * CX_ST + col];
                bb[n][0] = packh2(f0, f1);
                bb[n][1] = packh2(f2, f3);
            }
#pragma unroll
            for (int m = 0; m < 3; m++)
#pragma unroll
                for (int n = 0; n < 4; n++) mma_f16(acc[m][n], af[m], bb[n]);
        }
        __syncthreads();
    }
#pragma unroll
    for (int m = 0; m < 3; m++)
#pragma unroll
        for (int n = 0; n < 4; n++) {
            int r = m * 16 + g;
            int col = nt * 256 + warp * 32 + n * 8 + t * 2;
            size_t base = ((size_t)(kc * BATCH + b) * NROW + r) * HIDDEN + col;
            *(float2*)(g_ctxp + base) = make_float2(acc[m][n][0], acc[m][n][1]);
            *(float2*)(g_ctxp + base + (size_t)8 * HIDDEN) =
                make_float2(acc[m][n][2], acc[m][n][3]);
        }
}

// ---------------- K6: o = sum_kc(ctxp) @ Wv_h^T per head -------------------
__global__ void __launch_bounds__(256) k_out1(const float* __restrict__ wkv) {
    int h = blockIdx.x, b = blockIdx.y;
    __shared__ float sC[4][64];
    __shared__ float sW[64][65];
    int tid = threadIdx.x;
    int xx = tid >> 6, d = tid & 63;
    float acc = 0.f;
    for (int j0 = 0; j0 < HIDDEN; j0 += 64) {
        __syncthreads();
        {
            float v = 0.f;
#pragma unroll
            for (int kc = 0; kc < KCH_CTX; kc++)
                v += g_ctxp[((size_t)(kc * BATCH + b) * NROW + h * 4 + xx) * HIDDEN + j0 + d];
            sC[xx][d] = v;
        }
        for (int i = tid; i < 64 * 64; i += 256) {
            int r = i >> 6, c = i & 63;
            sW[r][c] = wkv[(size_t)(HIDDEN + h * 64 + r) * HIDDEN + j0 + c];
        }
        __syncthreads();
#pragma unroll
        for (int jj = 0; jj < 64; jj++) acc += sC[xx][jj] * sW[d][jj];
    }
    g_o[(size_t)(b * 4 + xx) * HIDDEN + h * 64 + d] = acc;
}

// ---------------- K7: out = o @ w_out^T + b_out ----------------------------
__global__ void __launch_bounds__(256) k_out2(const float* __restrict__ wout,
                                              const float* __restrict__ bout,
                                              float* __restrict__ out) {
    int e0 = blockIdx.x * 256, b = blockIdx.y;
    __shared__ float sO[4][HIDDEN];
    __shared__ float sW[256][33];
    int tid = threadIdx.x;
    for (int i = tid; i < 4 * HIDDEN; i += 256) {
        int r = i / HIDDEN, c = i % HIDDEN;
        sO[r][c] = g_o[(size_t)(b * 4 + r) * HIDDEN + c];
    }
    float a0 = 0.f, a1 = 0.f, a2 = 0.f, a3 = 0.f;
    for (int kc = 0; kc < 24; kc++) {
        int k0 = kc * 32;
        __syncthreads();
        for (int i = tid; i < 256 * 32; i += 256) {
            int r = i >> 5, c = i & 31;
            sW[r][c] = wout[(size_t)(e0 + r) * HIDDEN + k0 + c];
        }
        __syncthreads();
#pragma unroll
        for (int kk = 0; kk < 32; kk++) {
            float w = sW[tid][kk];
            a0 += sO[0][k0 + kk] * w;
            a1 += sO[1][k0 + kk] * w;
            a2 += sO[2][k0 + kk] * w;
            a3 += sO[3][k0 + kk] * w;
        }
    }
    float bb = bout[e0 + tid];
    out[(size_t)(b * 4 + 0) * HIDDEN + e0 + tid] = a0 + bb;
    out[(size_t)(b * 4 + 1) * HIDDEN + e0 + tid] = a1 + bb;
    out[(size_t)(b * 4 + 2) * HIDDEN + e0 + tid] = a2 + bb;
    out[(size_t)(b * 4 + 3) * HIDDEN + e0 + tid] = a3 + bb;
}

// ---------------- entry -----------------------------------------------------
extern "C" void kernel_launch(void* const* d_in, const int* in_sizes, int n_in,
                              void* d_out, int out_size) {
    const float* x     = (const float*)d_in[0];
    const float* w_kv  = (const float*)d_in[1];
    const float* w_q   = (const float*)d_in[2];
    const float* w_out = (const float*)d_in[3];
    const float* b_out = (const float*)d_in[4];
    float* out = (float*)d_out;

    const int smem_logits = (2 * LQ_SZ + 2 * LX_SZ) * 4;   // 81408 B
    const int smem_ctx    = (2 * CA_SZ + 2 * CX_SZ) * 4;   // 74240 B
    cudaFuncSetAttribute(k_logits, cudaFuncAttributeMaxDynamicSharedMemorySize, smem_logits);
    cudaFuncSetAttribute(k_ctx, cudaFuncAttributeMaxDynamicSharedMemorySize, smem_ctx);

    // qproj split in two: k_logits is our launch #4 -> lands in ncu's captured slot
    k_qproj<<<dim3(3, 8), 256>>>(x, w_q, 0);
    k_qproj<<<dim3(3, 8), 256>>>(x, w_q, 3);
    k_qk<<<dim3(12, 8), 256>>>(w_kv);
    k_logits<<<dim3(32, 8), 256, smem_logits>>>(x);
    k_rowstats<<<BATCH * NROW, 512>>>();
    k_ctx<<<dim3(3, KCH_CTX, 8), 256, smem_ctx>>>(x);
    k_out1<<<dim3(12, 8), 256>>>(w_kv);
    k_out2<<<dim3(3, 8), 256>>>(w_out, b_out, out);
}

// round 7
// speedup vs baseline: 1.0412x; 1.0412x over previous
#include <cuda_runtime.h>
#include <cuda_fp16.h>
#include <cstdint>

#define NUM_HEADS 12
#define NUM_BN 4
#define HIDDEN 768
#define HEAD_DIM 64
#define BATCH 8
#define SEQ 8192
#define NROW 48
#define SCALE 0.125f
#define KCH_CTX 8
#define TOK_PER_KC (SEQ / KCH_CTX)   // 1024

// ---------------- scratch -------------------------------------------------
__device__ float  g_q[BATCH * NUM_BN * HIDDEN];
__device__ __half g_qk[BATCH * NROW * HIDDEN];
__device__ float  g_logits[(size_t)BATCH * NROW * SEQ];
__device__ __half g_probs[(size_t)BATCH * NROW * SEQ];
__device__ float  g_ctxp[(size_t)KCH_CTX * BATCH * NROW * HIDDEN];
__device__ float  g_o[BATCH * NUM_BN * HIDDEN];

// ---------------- helpers -------------------------------------------------
__device__ __forceinline__ void mma_f16(float* d, const uint32_t* a, const uint32_t* b) {
    asm volatile(
        "mma.sync.aligned.m16n8k16.row.col.f32.f16.f16.f32 "
        "{%0,%1,%2,%3}, {%4,%5,%6,%7}, {%8,%9}, {%0,%1,%2,%3};"
        : "+f"(d[0]), "+f"(d[1]), "+f"(d[2]), "+f"(d[3])
        : "r"(a[0]), "r"(a[1]), "r"(a[2]), "r"(a[3]), "r"(b[0]), "r"(b[1]));
}
__device__ __forceinline__ uint32_t packh2(float lo, float hi) {
    uint32_t r;
    asm("cvt.rn.f16x2.f32 %0, %1, %2;" : "=r"(r) : "f"(hi), "f"(lo));
    return r;
}
__device__ __forceinline__ void cp16(void* dst_smem, const void* src_gmem) {
    uint32_t d = (uint32_t)__cvta_generic_to_shared(dst_smem);
    asm volatile("cp.async.cg.shared.global [%0], [%1], 16;" :: "r"(d), "l"(src_gmem));
}
__device__ __forceinline__ void cp_commit() { asm volatile("cp.async.commit_group;"); }
__device__ __forceinline__ void cp_wait1() { asm volatile("cp.async.wait_group 1;"); }
__device__ __forceinline__ void cp_wait0() { asm volatile("cp.async.wait_group 0;"); }

// ---------------- K1: fused q-proj + qk  (one launch) ----------------------
// grid (6, 8), 256 thr. Block bx: q dims [bx*128, +128) = heads {2bx, 2bx+1},
// then qk rows for those 2 heads (8 rows of g_qk).
__global__ void __launch_bounds__(256) k_qprojqk(const float* __restrict__ x,
                                                 const float* __restrict__ wq,
                                                 const float* __restrict__ wkv) {
    __shared__ float sX[4][HIDDEN];          // 12 KB
    __shared__ float sWpool[128 * 65];       // 33.3 KB (aliased in phase 2)
    __shared__ float sQ[4][128];             // 2 KB
    int b = blockIdx.y, bx = blockIdx.x, o0 = bx * 128;
    int tid = threadIdx.x;

    for (int i = tid; i < 4 * HIDDEN; i += 256) {
        int r = i / HIDDEN, c = i % HIDDEN;
        sX[r][c] = x[((size_t)b * SEQ + r) * HIDDEN + c];
    }
    int ol = tid & 127, xp = tid >> 7;
    float acc0 = 0.f, acc1 = 0.f;
    for (int kc = 0; kc < 12; kc++) {
        int k0 = kc * 64;
        __syncthreads();
        for (int i = tid; i < 128 * 64; i += 256) {
            int r = i >> 6, c = i & 63;
            sWpool[r * 65 + c] = wq[(size_t)(o0 + r) * HIDDEN + k0 + c];
        }
        __syncthreads();
#pragma unroll 8
        for (int kk = 0; kk < 64; kk++) {
            float w = sWpool[ol * 65 + kk];
            acc0 += sX[xp * 2][k0 + kk] * w;
            acc1 += sX[xp * 2 + 1][k0 + kk] * w;
        }
    }
    __syncthreads();
    sQ[xp * 2][ol] = acc0;
    sQ[xp * 2 + 1][ol] = acc1;

    // phase 2: qk for heads 2bx, 2bx+1 using sQ (d-local index 0..127)
    for (int n0 = 0; n0 < HIDDEN; n0 += 256) {
        float aa[8];
#pragma unroll
        for (int i = 0; i < 8; i++) aa[i] = 0.f;
        for (int kc = 0; kc < 4; kc++) {          // 4 x 32 d-rows
            __syncthreads();
            for (int i = tid; i < 32 * 256; i += 256) {
                int r = i >> 8, c = i & 255;
                sWpool[r * 257 + c] = wkv[(size_t)(o0 + kc * 32 + r) * HIDDEN + n0 + c];
            }
            __syncthreads();
            int hh = kc >> 1;
#pragma unroll
            for (int d = 0; d < 32; d++) {
                float w = sWpool[d * 257 + tid];
                int dl = kc * 32 + d;
                aa[hh * 4 + 0] += sQ[0][dl] * w;
                aa[hh * 4 + 1] += sQ[1][dl] * w;
                aa[hh * 4 + 2] += sQ[2][dl] * w;
                aa[hh * 4 + 3] += sQ[3][dl] * w;
            }
        }
#pragma unroll
        for (int hh = 0; hh < 2; hh++)
#pragma unroll
            for (int xx = 0; xx < 4; xx++) {
                size_t row = (size_t)b * NROW + (2 * bx + hh) * 4 + xx;
                g_qk[row * HIDDEN + n0 + tid] = __float2half(aa[hh * 4 + xx] * SCALE);
            }
    }
}

// ---------------- K2: logits = qk @ x^T, fp16 mma (unchanged; 61% DRAM) ----
#define LQ_ST 20
#define LX_ST 36
#define LQ_SZ (48 * LQ_ST)
#define LX_SZ (256 * LX_ST)
__global__ void __launch_bounds__(256) k_logits(const float* __restrict__ x) {
    extern __shared__ uint32_t sm32[];
    float* smf = (float*)sm32;
    int b = blockIdx.y;
    int tok0 = blockIdx.x * 256;
    int tid = threadIdx.x;
    int warp = tid >> 5, lane = tid & 31;
    int g = lane >> 2, t = lane & 3;
    const float* xb = x + (size_t)b * SEQ * HIDDEN;
    const __half* qb = g_qk + (size_t)b * NROW * HIDDEN;

    float acc[3][4][4];
#pragma unroll
    for (int m = 0; m < 3; m++)
#pragma unroll
        for (int n = 0; n < 4; n++)
#pragma unroll
            for (int i = 0; i < 4; i++) acc[m][n][i] = 0.f;

    auto stage = [&](int kc, int s) {
        int k0 = kc * 32;
        if (tid < 192) {
            int r = tid >> 2, c4 = tid & 3;
            cp16(sm32 + s * LQ_SZ + r * LQ_ST + c4 * 4,
                 qb + (size_t)r * HIDDEN + k0 + c4 * 8);
        }
        uint32_t* xs = sm32 + 2 * LQ_SZ + s * LX_SZ;
#pragma unroll
        for (int i = 0; i < 8; i++) {
            int idx = tid + i * 256;
            int r = idx >> 3, c4 = idx & 7;
            cp16(xs + r * LX_ST + c4 * 4, xb + (size_t)(tok0 + r) * HIDDEN + k0 + c4 * 4);
        }
        cp_commit();
    };

    stage(0, 0);
    for (int kc = 0; kc < 24; kc++) {
        int s = kc & 1;
        if (kc + 1 < 24) { stage(kc + 1, s ^ 1); cp_wait1(); }
        else             { cp_wait0(); }
        __syncthreads();
        const uint32_t* q = sm32 + s * LQ_SZ;
        const float* xs = smf + 2 * LQ_SZ + s * LX_SZ;
#pragma unroll
        for (int ks = 0; ks < 2; ks++) {
            int kk = ks * 16, kk2 = ks * 8;
            uint32_t a[3][4], bb[4][2];
#pragma unroll
            for (int m = 0; m < 3; m++) {
                int r0 = m * 16 + g;
                a[m][0] = q[r0 * LQ_ST + kk2 + t];
                a[m][1] = q[(r0 + 8) * LQ_ST + kk2 + t];
                a[m][2] = q[r0 * LQ_ST + kk2 + t + 4];
                a[m][3] = q[(r0 + 8) * LQ_ST + kk2 + t + 4];
            }
#pragma unroll
            for (int n = 0; n < 4; n++) {
                int row = warp * 32 + n * 8 + g;
                float2 p0 = *(const float2*)(xs + row * LX_ST + kk + 2 * t);
                float2 p1 = *(const float2*)(xs + row * LX_ST + kk + 2 * t + 8);
                bb[n][0] = packh2(p0.x, p0.y);
                bb[n][1] = packh2(p1.x, p1.y);
            }
#pragma unroll
            for (int m = 0; m < 3; m++)
#pragma unroll
                for (int n = 0; n < 4; n++) mma_f16(acc[m][n], a[m], bb[n]);
        }
        __syncthreads();
    }
#pragma unroll
    for (int m = 0; m < 3; m++)
#pragma unroll
        for (int n = 0; n < 4; n++) {
            int r = m * 16 + g;
            int col = tok0 + warp * 32 + n * 8 + t * 2;
            *(float2*)(g_logits + ((size_t)b * NROW + r) * SEQ + col) =
                make_float2(acc[m][n][0], acc[m][n][1]);
            *(float2*)(g_logits + ((size_t)b * NROW + r + 8) * SEQ + col) =
                make_float2(acc[m][n][2], acc[m][n][3]);
        }
}

// ---------------- K3: softmax: fp32 logits -> fp16 probs -------------------
__global__ void __launch_bounds__(512) k_rowstats() {
    int row = blockIdx.x;
    const float* lp = g_logits + (size_t)row * SEQ;
    __half2* pp = (__half2*)(g_probs + (size_t)row * SEQ);
    int tid = threadIdx.x;
    float4 v[4];
#pragma unroll
    for (int i = 0; i < 4; i++) v[i] = ((const float4*)lp)[i * 512 + tid];

    float m = -3.4e38f;
#pragma unroll
    for (int i = 0; i < 4; i++)
        m = fmaxf(m, fmaxf(fmaxf(v[i].x, v[i].y), fmaxf(v[i].z, v[i].w)));
    __shared__ float red[16];
#pragma unroll
    for (int o = 16; o > 0; o >>= 1) m = fmaxf(m, __shfl_xor_sync(0xffffffffu, m, o));
    if ((tid & 31) == 0) red[tid >> 5] = m;
    __syncthreads();
    if (tid < 32) {
        float v2 = (tid < 16) ? red[tid] : -3.4e38f;
#pragma unroll
        for (int o = 8; o > 0; o >>= 1) v2 = fmaxf(v2, __shfl_xor_sync(0xffffffffu, v2, o));
        if (tid == 0) red[0] = v2;
    }
    __syncthreads();
    m = red[0];

    float s = 0.f;
#pragma unroll
    for (int i = 0; i < 4; i++) {
        v[i].x = __expf(v[i].x - m);
        v[i].y = __expf(v[i].y - m);
        v[i].z = __expf(v[i].z - m);
        v[i].w = __expf(v[i].w - m);
        s += (v[i].x + v[i].y) + (v[i].z + v[i].w);
    }
    __shared__ float red2[16];
#pragma unroll
    for (int o = 16; o > 0; o >>= 1) s += __shfl_xor_sync(0xffffffffu, s, o);
    if ((tid & 31) == 0) red2[tid >> 5] = s;
    __syncthreads();
    if (tid < 32) {
        float v2 = (tid < 16) ? red2[tid] : 0.f;
#pragma unroll
        for (int o = 8; o > 0; o >>= 1) v2 += __shfl_xor_sync(0xffffffffu, v2, o);
        if (tid == 0) red2[0] = v2;
    }
    __syncthreads();
    float inv = 1.0f / red2[0];

#pragma unroll
    for (int i = 0; i < 4; i++) {
        int idx = i * 512 + tid;
        pp[idx * 2 + 0] = __floats2half2_rn(v[i].x * inv, v[i].y * inv);
        pp[idx * 2 + 1] = __floats2half2_rn(v[i].z * inv, v[i].w * inv);
    }
}

// ---------------- K4: ctx partials = probs @ x ------------------------------
// v2: x (B-operand) loaded DIRECTLY from gmem into registers (no smem => no
// bank conflicts); probs (A) staged via cp.async, conflict-free stride 20.
// grid (3 nt, 8 kc, 8 b), 256 thr. Tile M=48, N=256, K=1024 tokens.
#define CA_ST 20
#define NCH_C 32
__global__ void __launch_bounds__(256) k_ctx(const float* __restrict__ x) {
    __shared__ uint32_t sA[2][48 * CA_ST];   // 7.5 KB
    int nt = blockIdx.x, kc = blockIdx.y, b = blockIdx.z;
    int tid = threadIdx.x;
    int warp = tid >> 5, lane = tid & 31;
    int g = lane >> 2, t = lane & 3;
    int tokbase = kc * TOK_PER_KC;
    const __half* pb = g_probs + (size_t)b * NROW * SEQ;
    // lane-fixed base: row = tokbase + 2t, col = nt*256 + warp*32 + g
    const float* xlane = x + ((size_t)b * SEQ + tokbase + 2 * t) * HIDDEN
                           + nt * 256 + warp * 32 + g;

    float acc[3][4][4];
#pragma unroll
    for (int m = 0; m < 3; m++)
#pragma unroll
        for (int n = 0; n < 4; n++)
#pragma unroll
            for (int i = 0; i < 4; i++) acc[m][n][i] = 0.f;

    auto stageA = [&](int ch, int s) {
        if (tid < 192) {
            int r = tid >> 2, c4 = tid & 3;
            cp16(&sA[s][r * CA_ST + c4 * 4],
                 pb + (size_t)r * SEQ + tokbase + ch * 32 + c4 * 8);
        }
        cp_commit();
    };
    // xf layout: [ks*16 + h*8 + e*4 + n], row = ch*32 + ks*16 + h*8 + e (+2t in base)
    auto loadB = [&](int ch, float* xf) {
#pragma unroll
        for (int ks = 0; ks < 2; ks++)
#pragma unroll
            for (int h = 0; h < 2; h++)
#pragma unroll
                for (int e = 0; e < 2; e++)
#pragma unroll
                    for (int n = 0; n < 4; n++)
                        xf[ks * 16 + h * 8 + e * 4 + n] =
                            __ldg(xlane + (size_t)(ch * 32 + ks * 16 + h * 8 + e) * HIDDEN + n * 8);
    };
    auto compute = [&](const uint32_t* As, const float* xf) {
#pragma unroll
        for (int ks = 0; ks < 2; ks++) {
            int kk2 = ks * 8;
            uint32_t af[3][4], bb[4][2];
#pragma unroll
            for (int m = 0; m < 3; m++) {
                int r0 = m * 16 + g;
                af[m][0] = As[r0 * CA_ST + kk2 + t];
                af[m][1] = As[(r0 + 8) * CA_ST + kk2 + t];
                af[m][2] = As[r0 * CA_ST + kk2 + t + 4];
                af[m][3] = As[(r0 + 8) * CA_ST + kk2 + t + 4];
            }
#pragma unroll
            for (int n = 0; n < 4; n++) {
                bb[n][0] = packh2(xf[ks * 16 + n], xf[ks * 16 + 4 + n]);
                bb[n][1] = packh2(xf[ks * 16 + 8 + n], xf[ks * 16 + 12 + n]);
            }
#pragma unroll
            for (int m = 0; m < 3; m++)
#pragma unroll
                for (int n = 0; n < 4; n++) mma_f16(acc[m][n], af[m], bb[n]);
        }
    };

    float xf0[32], xf1[32];
    stageA(0, 0);
    loadB(0, xf0);
#pragma unroll 1
    for (int ch = 0; ch < NCH_C; ch += 2) {
        if (ch + 1 < NCH_C) { stageA(ch + 1, 1); loadB(ch + 1, xf1); cp_wait1(); }
        else { cp_wait0(); }
        __syncthreads();
        compute(sA[0], xf0);
        __syncthreads();
        if (ch + 2 < NCH_C) { stageA(ch + 2, 0); loadB(ch + 2, xf0); cp_wait1(); }
        else { cp_wait0(); }
        __syncthreads();
        compute(sA[1], xf1);
        __syncthreads();
    }

#pragma unroll
    for (int m = 0; m < 3; m++)
#pragma unroll
        for (int n = 0; n < 4; n++) {
            int r = m * 16 + g;
            int col = nt * 256 + warp * 32 + n * 8 + t * 2;
            size_t base = ((size_t)(kc * BATCH + b) * NROW + r) * HIDDEN + col;
            *(float2*)(g_ctxp + base) = make_float2(acc[m][n][0], acc[m][n][1]);
            *(float2*)(g_ctxp + base + (size_t)8 * HIDDEN) =
                make_float2(acc[m][n][2], acc[m][n][3]);
        }
}

// ---------------- K5: o = sum_kc(ctxp) @ Wv_h^T per head -------------------
__global__ void __launch_bounds__(256) k_out1(const float* __restrict__ wkv) {
    int h = blockIdx.x, b = blockIdx.y;
    __shared__ float sC[4][64];
    __shared__ float sW[64][65];
    int tid = threadIdx.x;
    int xx = tid >> 6, d = tid & 63;
    float acc = 0.f;
    for (int j0 = 0; j0 < HIDDEN; j0 += 64) {
        __syncthreads();
        {
            float v = 0.f;
#pragma unroll
            for (int kc = 0; kc < KCH_CTX; kc++)
                v += g_ctxp[((size_t)(kc * BATCH + b) * NROW + h * 4 + xx) * HIDDEN + j0 + d];
            sC[xx][d] = v;
        }
        for (int i = tid; i < 64 * 64; i += 256) {
            int r = i >> 6, c = i & 63;
            sW[r][c] = wkv[(size_t)(HIDDEN + h * 64 + r) * HIDDEN + j0 + c];
        }
        __syncthreads();
#pragma unroll
        for (int jj = 0; jj < 64; jj++) acc += sC[xx][jj] * sW[d][jj];
    }
    g_o[(size_t)(b * 4 + xx) * HIDDEN + h * 64 + d] = acc;
}

// ---------------- K6: out = o @ w_out^T + b_out ----------------------------
__global__ void __launch_bounds__(256) k_out2(const float* __restrict__ wout,
                                              const float* __restrict__ bout,
                                              float* __restrict__ out) {
    int e0 = blockIdx.x * 256, b = blockIdx.y;
    __shared__ float sO[4][HIDDEN];
    __shared__ float sW[256][33];
    int tid = threadIdx.x;
    for (int i = tid; i < 4 * HIDDEN; i += 256) {
        int r = i / HIDDEN, c = i % HIDDEN;
        sO[r][c] = g_o[(size_t)(b * 4 + r) * HIDDEN + c];
    }
    float a0 = 0.f, a1 = 0.f, a2 = 0.f, a3 = 0.f;
    for (int kc = 0; kc < 24; kc++) {
        int k0 = kc * 32;
        __syncthreads();
        for (int i = tid; i < 256 * 32; i += 256) {
            int r = i >> 5, c = i & 31;
            sW[r][c] = wout[(size_t)(e0 + r) * HIDDEN + k0 + c];
        }
        __syncthreads();
#pragma unroll
        for (int kk = 0; kk < 32; kk++) {
            float w = sW[tid][kk];
            a0 += sO[0][k0 + kk] * w;
            a1 += sO[1][k0 + kk] * w;
            a2 += sO[2][k0 + kk] * w;
            a3 += sO[3][k0 + kk] * w;
        }
    }
    float bb = bout[e0 + tid];
    out[(size_t)(b * 4 + 0) * HIDDEN + e0 + tid] = a0 + bb;
    out[(size_t)(b * 4 + 1) * HIDDEN + e0 + tid] = a1 + bb;
    out[(size_t)(b * 4 + 2) * HIDDEN + e0 + tid] = a2 + bb;
    out[(size_t)(b * 4 + 3) * HIDDEN + e0 + tid] = a3 + bb;
}

// ---------------- entry -----------------------------------------------------
extern "C" void kernel_launch(void* const* d_in, const int* in_sizes, int n_in,
                              void* d_out, int out_size) {
    const float* x     = (const float*)d_in[0];
    const float* w_kv  = (const float*)d_in[1];
    const float* w_q   = (const float*)d_in[2];
    const float* w_out = (const float*)d_in[3];
    const float* b_out = (const float*)d_in[4];
    float* out = (float*)d_out;

    const int smem_logits = (2 * LQ_SZ + 2 * LX_SZ) * 4;   // 81408 B
    cudaFuncSetAttribute(k_logits, cudaFuncAttributeMaxDynamicSharedMemorySize, smem_logits);

    // launch order puts k_ctx in ncu's captured slot (#4)
    k_qprojqk<<<dim3(6, 8), 256>>>(x, w_q, w_kv);
    k_logits<<<dim3(32, 8), 256, smem_logits>>>(x);
    k_rowstats<<<BATCH * NROW, 512>>>();
    k_ctx<<<dim3(3, KCH_CTX, 8), 256>>>(x);
    k_out1<<<dim3(12, 8), 256>>>(w_kv);
    k_out2<<<dim3(3, 8), 256>>>(w_out, b_out, out);
}

// round 8
// speedup vs baseline: 2.8597x; 2.7466x over previous
#include <cuda_runtime.h>
#include <cuda_fp16.h>
#include <cstdint>

#define NUM_HEADS 12
#define NUM_BN 4
#define HIDDEN 768
#define HEAD_DIM 64
#define BATCH 8
#define SEQ 8192
#define NROW 48
#define SCALE 0.125f
#define KCH_CTX 16
#define TOK_PER_KC (SEQ / KCH_CTX)   // 512

// ---------------- scratch -------------------------------------------------
__device__ float  g_q[BATCH * NUM_BN * HIDDEN];
__device__ __half g_qk[BATCH * NROW * HIDDEN];
__device__ float  g_logits[(size_t)BATCH * NROW * SEQ];
__device__ __half g_probs[(size_t)BATCH * NROW * SEQ];
__device__ float  g_ctxp[(size_t)KCH_CTX * BATCH * NROW * HIDDEN];   // 18.9 MB
__device__ float  g_ctx[BATCH * NROW * HIDDEN];
__device__ float  g_o[BATCH * NUM_BN * HIDDEN];

// ---------------- helpers -------------------------------------------------
__device__ __forceinline__ void mma_f16(float* d, const uint32_t* a, const uint32_t* b) {
    asm volatile(
        "mma.sync.aligned.m16n8k16.row.col.f32.f16.f16.f32 "
        "{%0,%1,%2,%3}, {%4,%5,%6,%7}, {%8,%9}, {%0,%1,%2,%3};"
        : "+f"(d[0]), "+f"(d[1]), "+f"(d[2]), "+f"(d[3])
        : "r"(a[0]), "r"(a[1]), "r"(a[2]), "r"(a[3]), "r"(b[0]), "r"(b[1]));
}
__device__ __forceinline__ uint32_t packh2(float lo, float hi) {
    uint32_t r;
    asm("cvt.rn.f16x2.f32 %0, %1, %2;" : "=r"(r) : "f"(hi), "f"(lo));
    return r;
}
__device__ __forceinline__ void cp16(void* dst_smem, const void* src_gmem) {
    uint32_t d = (uint32_t)__cvta_generic_to_shared(dst_smem);
    asm volatile("cp.async.cg.shared.global [%0], [%1], 16;" :: "r"(d), "l"(src_gmem));
}
__device__ __forceinline__ void cp_commit() { asm volatile("cp.async.commit_group;"); }
__device__ __forceinline__ void cp_wait1() { asm volatile("cp.async.wait_group 1;"); }
__device__ __forceinline__ void cp_wait0() { asm volatile("cp.async.wait_group 0;"); }

// ---------------- K1: q = x[:, :4] @ w_q^T  (warp-per-output) --------------
// 768 blocks x 256 thr = 6144 warps; warp (b, o) computes 4 token outputs.
__global__ void __launch_bounds__(256) k_qproj(const float* __restrict__ x,
                                               const float* __restrict__ wq) {
    int gw = blockIdx.x * 8 + (threadIdx.x >> 5);
    int lane = threadIdx.x & 31;
    int b = gw / HIDDEN, o = gw % HIDDEN;
    const float4* wr = (const float4*)(wq + (size_t)o * HIDDEN);
    const float4* xr = (const float4*)(x + (size_t)b * SEQ * HIDDEN);
    float acc[4] = {0.f, 0.f, 0.f, 0.f};
#pragma unroll
    for (int i = 0; i < 6; i++) {
        float4 w4 = wr[lane + 32 * i];
#pragma unroll
        for (int xx = 0; xx < 4; xx++) {
            float4 x4 = xr[xx * (HIDDEN / 4) + lane + 32 * i];
            acc[xx] += w4.x * x4.x + w4.y * x4.y + w4.z * x4.z + w4.w * x4.w;
        }
    }
#pragma unroll
    for (int xx = 0; xx < 4; xx++)
#pragma unroll
        for (int off = 16; off; off >>= 1)
            acc[xx] += __shfl_xor_sync(0xffffffffu, acc[xx], off);
    if (lane == 0) {
#pragma unroll
        for (int xx = 0; xx < 4; xx++)
            g_q[(size_t)(b * 4 + xx) * HIDDEN + o] = acc[xx];
    }
}

// ---------------- K2: qk = SCALE * q_h @ Wk_h -> fp16 ----------------------
// grid (3 nchunk, 12 h, 8 b), 256 thr. Thread = one n; coalesced weight rows.
__global__ void __launch_bounds__(256) k_qk(const float* __restrict__ wkv) {
    __shared__ float sq[4][64];
    int h = blockIdx.y, b = blockIdx.z;
    int tid = threadIdx.x;
    sq[tid >> 6][tid & 63] = g_q[(size_t)(b * 4 + (tid >> 6)) * HIDDEN + h * 64 + (tid & 63)];
    __syncthreads();
    int n = blockIdx.x * 256 + tid;
    const float* wp = wkv + (size_t)(h * 64) * HIDDEN + n;
    float a0 = 0.f, a1 = 0.f, a2 = 0.f, a3 = 0.f;
#pragma unroll 8
    for (int d = 0; d < 64; d++) {
        float w = wp[(size_t)d * HIDDEN];
        a0 += sq[0][d] * w;
        a1 += sq[1][d] * w;
        a2 += sq[2][d] * w;
        a3 += sq[3][d] * w;
    }
    size_t rb = (size_t)(b * NROW + h * 4) * HIDDEN + n;
    g_qk[rb] = __float2half(a0 * SCALE);
    g_qk[rb + HIDDEN] = __float2half(a1 * SCALE);
    g_qk[rb + 2 * HIDDEN] = __float2half(a2 * SCALE);
    g_qk[rb + 3 * HIDDEN] = __float2half(a3 * SCALE);
}

// ---------------- K3: logits = qk @ x^T, fp16 mma (42.7us, 61% DRAM) -------
#define LQ_ST 20
#define LX_ST 36
#define LQ_SZ (48 * LQ_ST)
#define LX_SZ (256 * LX_ST)
__global__ void __launch_bounds__(256) k_logits(const float* __restrict__ x) {
    extern __shared__ uint32_t sm32[];
    float* smf = (float*)sm32;
    int b = blockIdx.y;
    int tok0 = blockIdx.x * 256;
    int tid = threadIdx.x;
    int warp = tid >> 5, lane = tid & 31;
    int g = lane >> 2, t = lane & 3;
    const float* xb = x + (size_t)b * SEQ * HIDDEN;
    const __half* qb = g_qk + (size_t)b * NROW * HIDDEN;

    float acc[3][4][4];
#pragma unroll
    for (int m = 0; m < 3; m++)
#pragma unroll
        for (int n = 0; n < 4; n++)
#pragma unroll
            for (int i = 0; i < 4; i++) acc[m][n][i] = 0.f;

    auto stage = [&](int kc, int s) {
        int k0 = kc * 32;
        if (tid < 192) {
            int r = tid >> 2, c4 = tid & 3;
            cp16(sm32 + s * LQ_SZ + r * LQ_ST + c4 * 4,
                 qb + (size_t)r * HIDDEN + k0 + c4 * 8);
        }
        uint32_t* xs = sm32 + 2 * LQ_SZ + s * LX_SZ;
#pragma unroll
        for (int i = 0; i < 8; i++) {
            int idx = tid + i * 256;
            int r = idx >> 3, c4 = idx & 7;
            cp16(xs + r * LX_ST + c4 * 4, xb + (size_t)(tok0 + r) * HIDDEN + k0 + c4 * 4);
        }
        cp_commit();
    };

    stage(0, 0);
    for (int kc = 0; kc < 24; kc++) {
        int s = kc & 1;
        if (kc + 1 < 24) { stage(kc + 1, s ^ 1); cp_wait1(); }
        else             { cp_wait0(); }
        __syncthreads();
        const uint32_t* q = sm32 + s * LQ_SZ;
        const float* xs = smf + 2 * LQ_SZ + s * LX_SZ;
#pragma unroll
        for (int ks = 0; ks < 2; ks++) {
            int kk = ks * 16, kk2 = ks * 8;
            uint32_t a[3][4], bb[4][2];
#pragma unroll
            for (int m = 0; m < 3; m++) {
                int r0 = m * 16 + g;
                a[m][0] = q[r0 * LQ_ST + kk2 + t];
                a[m][1] = q[(r0 + 8) * LQ_ST + kk2 + t];
                a[m][2] = q[r0 * LQ_ST + kk2 + t + 4];
                a[m][3] = q[(r0 + 8) * LQ_ST + kk2 + t + 4];
            }
#pragma unroll
            for (int n = 0; n < 4; n++) {
                int row = warp * 32 + n * 8 + g;
                float2 p0 = *(const float2*)(xs + row * LX_ST + kk + 2 * t);
                float2 p1 = *(const float2*)(xs + row * LX_ST + kk + 2 * t + 8);
                bb[n][0] = packh2(p0.x, p0.y);
                bb[n][1] = packh2(p1.x, p1.y);
            }
#pragma unroll
            for (int m = 0; m < 3; m++)
#pragma unroll
                for (int n = 0; n < 4; n++) mma_f16(acc[m][n], a[m], bb[n]);
        }
        __syncthreads();
    }
#pragma unroll
    for (int m = 0; m < 3; m++)
#pragma unroll
        for (int n = 0; n < 4; n++) {
            int r = m * 16 + g;
            int col = tok0 + warp * 32 + n * 8 + t * 2;
            *(float2*)(g_logits + ((size_t)b * NROW + r) * SEQ + col) =
                make_float2(acc[m][n][0], acc[m][n][1]);
            *(float2*)(g_logits + ((size_t)b * NROW + r + 8) * SEQ + col) =
                make_float2(acc[m][n][2], acc[m][n][3]);
        }
}

// ---------------- K4: softmax: fp32 logits -> fp16 probs -------------------
__global__ void __launch_bounds__(512) k_rowstats() {
    int row = blockIdx.x;
    const float* lp = g_logits + (size_t)row * SEQ;
    __half2* pp = (__half2*)(g_probs + (size_t)row * SEQ);
    int tid = threadIdx.x;
    float4 v[4];
#pragma unroll
    for (int i = 0; i < 4; i++) v[i] = ((const float4*)lp)[i * 512 + tid];

    float m = -3.4e38f;
#pragma unroll
    for (int i = 0; i < 4; i++)
        m = fmaxf(m, fmaxf(fmaxf(v[i].x, v[i].y), fmaxf(v[i].z, v[i].w)));
    __shared__ float red[16];
#pragma unroll
    for (int o = 16; o > 0; o >>= 1) m = fmaxf(m, __shfl_xor_sync(0xffffffffu, m, o));
    if ((tid & 31) == 0) red[tid >> 5] = m;
    __syncthreads();
    if (tid < 32) {
        float v2 = (tid < 16) ? red[tid] : -3.4e38f;
#pragma unroll
        for (int o = 8; o > 0; o >>= 1) v2 = fmaxf(v2, __shfl_xor_sync(0xffffffffu, v2, o));
        if (tid == 0) red[0] = v2;
    }
    __syncthreads();
    m = red[0];

    float s = 0.f;
#pragma unroll
    for (int i = 0; i < 4; i++) {
        v[i].x = __expf(v[i].x - m);
        v[i].y = __expf(v[i].y - m);
        v[i].z = __expf(v[i].z - m);
        v[i].w = __expf(v[i].w - m);
        s += (v[i].x + v[i].y) + (v[i].z + v[i].w);
    }
    __shared__ float red2[16];
#pragma unroll
    for (int o = 16; o > 0; o >>= 1) s += __shfl_xor_sync(0xffffffffu, s, o);
    if ((tid & 31) == 0) red2[tid >> 5] = s;
    __syncthreads();
    if (tid < 32) {
        float v2 = (tid < 16) ? red2[tid] : 0.f;
#pragma unroll
        for (int o = 8; o > 0; o >>= 1) v2 += __shfl_xor_sync(0xffffffffu, v2, o);
        if (tid == 0) red2[0] = v2;
    }
    __syncthreads();
    float inv = 1.0f / red2[0];

#pragma unroll
    for (int i = 0; i < 4; i++) {
        int idx = i * 512 + tid;
        pp[idx * 2 + 0] = __floats2half2_rn(v[i].x * inv, v[i].y * inv);
        pp[idx * 2 + 1] = __floats2half2_rn(v[i].z * inv, v[i].w * inv);
    }
}

// ---------------- K5: ctx partials = probs @ x ------------------------------
// x (B) loaded straight to registers (no smem); probs via cp.async (stride 20).
// grid (3 nt, 16 kc, 8 b) = 384 CTAs, 256 thr. Tile M=48, N=256, K=512 tokens.
#define CA_ST 20
#define NCH_C (TOK_PER_KC / 32)   // 16
__global__ void __launch_bounds__(256) k_ctx(const float* __restrict__ x) {
    __shared__ uint32_t sA[2][48 * CA_ST];
    int nt = blockIdx.x, kc = blockIdx.y, b = blockIdx.z;
    int tid = threadIdx.x;
    int warp = tid >> 5, lane = tid & 31;
    int g = lane >> 2, t = lane & 3;
    int tokbase = kc * TOK_PER_KC;
    const __half* pb = g_probs + (size_t)b * NROW * SEQ;
    const float* xlane = x + ((size_t)b * SEQ + tokbase + 2 * t) * HIDDEN
                           + nt * 256 + warp * 32 + g;

    float acc[3][4][4];
#pragma unroll
    for (int m = 0; m < 3; m++)
#pragma unroll
        for (int n = 0; n < 4; n++)
#pragma unroll
            for (int i = 0; i < 4; i++) acc[m][n][i] = 0.f;

    auto stageA = [&](int ch, int s) {
        if (tid < 192) {
            int r = tid >> 2, c4 = tid & 3;
            cp16(&sA[s][r * CA_ST + c4 * 4],
                 pb + (size_t)r * SEQ + tokbase + ch * 32 + c4 * 8);
        }
        cp_commit();
    };
    auto loadB = [&](int ch, float* xf) {
#pragma unroll
        for (int ks = 0; ks < 2; ks++)
#pragma unroll
            for (int h = 0; h < 2; h++)
#pragma unroll
                for (int e = 0; e < 2; e++)
#pragma unroll
                    for (int n = 0; n < 4; n++)
                        xf[ks * 16 + h * 8 + e * 4 + n] =
                            __ldg(xlane + (size_t)(ch * 32 + ks * 16 + h * 8 + e) * HIDDEN + n * 8);
    };
    auto compute = [&](const uint32_t* As, const float* xf) {
#pragma unroll
        for (int ks = 0; ks < 2; ks++) {
            int kk2 = ks * 8;
            uint32_t af[3][4], bb[4][2];
#pragma unroll
            for (int m = 0; m < 3; m++) {
                int r0 = m * 16 + g;
                af[m][0] = As[r0 * CA_ST + kk2 + t];
                af[m][1] = As[(r0 + 8) * CA_ST + kk2 + t];
                af[m][2] = As[r0 * CA_ST + kk2 + t + 4];
                af[m][3] = As[(r0 + 8) * CA_ST + kk2 + t + 4];
            }
#pragma unroll
            for (int n = 0; n < 4; n++) {
                bb[n][0] = packh2(xf[ks * 16 + n], xf[ks * 16 + 4 + n]);
                bb[n][1] = packh2(xf[ks * 16 + 8 + n], xf[ks * 16 + 12 + n]);
            }
#pragma unroll
            for (int m = 0; m < 3; m++)
#pragma unroll
                for (int n = 0; n < 4; n++) mma_f16(acc[m][n], af[m], bb[n]);
        }
    };

    float xf0[32], xf1[32];
    stageA(0, 0);
    loadB(0, xf0);
#pragma unroll 1
    for (int ch = 0; ch < NCH_C; ch += 2) {
        if (ch + 1 < NCH_C) { stageA(ch + 1, 1); loadB(ch + 1, xf1); cp_wait1(); }
        else { cp_wait0(); }
        __syncthreads();
        compute(sA[0], xf0);
        __syncthreads();
        if (ch + 2 < NCH_C) { stageA(ch + 2, 0); loadB(ch + 2, xf0); cp_wait1(); }
        else { cp_wait0(); }
        __syncthreads();
        compute(sA[1], xf1);
        __syncthreads();
    }

#pragma unroll
    for (int m = 0; m < 3; m++)
#pragma unroll
        for (int n = 0; n < 4; n++) {
            int r = m * 16 + g;
            int col = nt * 256 + warp * 32 + n * 8 + t * 2;
            size_t base = ((size_t)(kc * BATCH + b) * NROW + r) * HIDDEN + col;
            *(float2*)(g_ctxp + base) = make_float2(acc[m][n][0], acc[m][n][1]);
            *(float2*)(g_ctxp + base + (size_t)8 * HIDDEN) =
                make_float2(acc[m][n][2], acc[m][n][3]);
        }
}

// ---------------- K6: reduce ctx partials -----------------------------------
// 288 blocks x 256 thr: exactly one float4 per thread.
__global__ void __launch_bounds__(256) k_reduce() {
    int idx = blockIdx.x * 256 + threadIdx.x;   // < 73728
    const float4* p = (const float4*)g_ctxp;
    float4 s = p[idx];
    const int STRIDE = BATCH * NROW * HIDDEN / 4;   // 73728
#pragma unroll
    for (int kc = 1; kc < KCH_CTX; kc++) {
        float4 v = p[(size_t)kc * STRIDE + idx];
        s.x += v.x; s.y += v.y; s.z += v.z; s.w += v.w;
    }
    ((float4*)g_ctx)[idx] = s;
}

// ---------------- K7: o = ctx @ Wv^T per head (warp-per-output) ------------
// 768 blocks x 256 thr; warp (b, od) computes 4 token outputs.
__global__ void __launch_bounds__(256) k_out1(const float* __restrict__ wkv) {
    int gw = blockIdx.x * 8 + (threadIdx.x >> 5);
    int lane = threadIdx.x & 31;
    int b = gw / HIDDEN, od = gw % HIDDEN;   // od = h*64+d
    int h = od >> 6;
    const float4* wr = (const float4*)(wkv + (size_t)(HIDDEN + od) * HIDDEN);
    float acc[4] = {0.f, 0.f, 0.f, 0.f};
#pragma unroll
    for (int i = 0; i < 6; i++) {
        float4 w4 = wr[lane + 32 * i];
#pragma unroll
        for (int xx = 0; xx < 4; xx++) {
            float4 c4 = ((const float4*)(g_ctx + (size_t)(b * NROW + h * 4 + xx) * HIDDEN))[lane + 32 * i];
            acc[xx] += w4.x * c4.x + w4.y * c4.y + w4.z * c4.z + w4.w * c4.w;
        }
    }
#pragma unroll
    for (int xx = 0; xx < 4; xx++)
#pragma unroll
        for (int off = 16; off; off >>= 1)
            acc[xx] += __shfl_xor_sync(0xffffffffu, acc[xx], off);
    if (lane == 0) {
#pragma unroll
        for (int xx = 0; xx < 4; xx++)
            g_o[(size_t)(b * 4 + xx) * HIDDEN + od] = acc[xx];
    }
}

// ---------------- K8: out = o @ w_out^T + b_out (warp-per-output) ----------
__global__ void __launch_bounds__(256) k_out2(const float* __restrict__ wout,
                                              const float* __restrict__ bout,
                                              float* __restrict__ out) {
    int gw = blockIdx.x * 8 + (threadIdx.x >> 5);
    int lane = threadIdx.x & 31;
    int b = gw / HIDDEN, e = gw % HIDDEN;
    const float4* wr = (const float4*)(wout + (size_t)e * HIDDEN);
    float acc[4] = {0.f, 0.f, 0.f, 0.f};
#pragma unroll
    for (int i = 0; i < 6; i++) {
        float4 w4 = wr[lane + 32 * i];
#pragma unroll
        for (int xx = 0; xx < 4; xx++) {
            float4 o4 = ((const float4*)(g_o + (size_t)(b * 4 + xx) * HIDDEN))[lane + 32 * i];
            acc[xx] += w4.x * o4.x + w4.y * o4.y + w4.z * o4.z + w4.w * o4.w;
        }
    }
#pragma unroll
    for (int xx = 0; xx < 4; xx++)
#pragma unroll
        for (int off = 16; off; off >>= 1)
            acc[xx] += __shfl_xor_sync(0xffffffffu, acc[xx], off);
    if (lane == 0) {
        float bb = bout[e];
#pragma unroll
        for (int xx = 0; xx < 4; xx++)
            out[(size_t)(b * 4 + xx) * HIDDEN + e] = acc[xx] + bb;
    }
}

// ---------------- entry -----------------------------------------------------
extern "C" void kernel_launch(void* const* d_in, const int* in_sizes, int n_in,
                              void* d_out, int out_size) {
    const float* x     = (const float*)d_in[0];
    const float* w_kv  = (const float*)d_in[1];
    const float* w_q   = (const float*)d_in[2];
    const float* w_out = (const float*)d_in[3];
    const float* b_out = (const float*)d_in[4];
    float* out = (float*)d_out;

    const int smem_logits = (2 * LQ_SZ + 2 * LX_SZ) * 4;   // 81408 B
    cudaFuncSetAttribute(k_logits, cudaFuncAttributeMaxDynamicSharedMemorySize, smem_logits);

    k_qproj<<<768, 256>>>(x, w_q);
    k_qk<<<dim3(3, 12, 8), 256>>>(w_kv);
    k_logits<<<dim3(32, 8), 256, smem_logits>>>(x);
    k_rowstats<<<BATCH * NROW, 512>>>();
    k_ctx<<<dim3(3, KCH_CTX, 8), 256>>>(x);
    k_reduce<<<288, 256>>>();
    k_out1<<<768, 256>>>(w_kv);
    k_out2<<<768, 256>>>(w_out, b_out, out);
}